// round 16
// baseline (speedup 1.0000x reference)
#include <cuda_runtime.h>
#include <cuda_fp16.h>
#include <math.h>
#include <stdint.h>

#define NROWS 65536

// ---------------- scratch (device globals; no allocation allowed) ----------
__device__ float  g_psum[128 * 768];
__device__ float  g_psumsq[128 * 768];
__device__ float  g_scale[768];
__device__ float  g_shift[768];
__device__ __half g_xh[(size_t)NROWS * 768];
__device__ __half g_W0[1536 * 768];
__device__ __half g_W1[1536 * 512];
__device__ __half g_h1h[(size_t)NROWS * 512];
__device__ float g_gc0[1536];
__device__ float g_gc1[1536];
__device__ double g_crfP[256][4];
__device__ double g_crfN[256];

// ---------------- helpers ----------------
__device__ __forceinline__ void cpasync16(uint32_t dst, const void* src) {
    asm volatile("cp.async.cg.shared.global [%0], [%1], 16;" :: "r"(dst), "l"(src));
}
#define CP_COMMIT() asm volatile("cp.async.commit_group;")

__device__ __forceinline__ void ldsm4(uint32_t& r0, uint32_t& r1, uint32_t& r2,
                                      uint32_t& r3, uint32_t addr) {
    asm volatile("ldmatrix.sync.aligned.m8n8.x4.shared.b16 {%0,%1,%2,%3}, [%4];"
                 : "=r"(r0), "=r"(r1), "=r"(r2), "=r"(r3) : "r"(addr));
}
__device__ __forceinline__ void mma16816h(float* c, const uint32_t* a, const uint32_t* b) {
    asm volatile("mma.sync.aligned.m16n8k16.row.col.f32.f16.f16.f32 "
                 "{%0,%1,%2,%3}, {%4,%5,%6,%7}, {%8,%9}, {%0,%1,%2,%3};"
                 : "+f"(c[0]), "+f"(c[1]), "+f"(c[2]), "+f"(c[3])
                 : "r"(a[0]), "r"(a[1]), "r"(a[2]), "r"(a[3]), "r"(b[0]), "r"(b[1]));
}

// fast activations: __expf = MUFU.EX2-based, rel err ~2^-21 (negligible here)
__device__ __forceinline__ float fsigmoid(float x) {
    return 1.f / (1.f + __expf(-x));
}
__device__ __forceinline__ float ftanh(float x) {
    return 1.f - 2.f / (1.f + __expf(2.f * x));
}

// ---------------- BN stats (per-block partials) -----------------------------
__global__ void stats_kernel(const float* __restrict__ x, int rowsPerBlock, int nrows) {
    int c = threadIdx.x;
    int b = blockIdx.x;
    long r0 = (long)b * rowsPerBlock;
    float s = 0.f, s2 = 0.f;
    for (int r = 0; r < rowsPerBlock; ++r) {
        long row = r0 + r;
        if (row < nrows) {
            float v = x[row * 768 + c];
            s += v; s2 += v * v;
        }
    }
    g_psum[b * 768 + c] = s;
    g_psumsq[b * 768 + c] = s2;
}

__global__ void prep_kernel(const float* __restrict__ gamma,
                            const float* __restrict__ beta, int nrows, int nblk) {
    int c = threadIdx.x;
    double s = 0.0, s2 = 0.0;
    for (int b = 0; b < nblk; ++b) {
        s  += (double)g_psum[b * 768 + c];
        s2 += (double)g_psumsq[b * 768 + c];
    }
    double mean = s / (double)nrows;
    double var  = s2 / (double)nrows - mean * mean;
    float sc = gamma[c] * (float)(1.0 / sqrt(var + 1e-5));
    g_scale[c] = sc;
    g_shift[c] = beta[c] - (float)mean * sc;
}

// ------------- merged L0 prep: split_x(fp16) + repackW0(fp16) + gconst0 ------
__global__ void prep_all_l0(const float4* __restrict__ x4,
                            const float* __restrict__ w,
                            const float* __restrict__ bih,
                            const float* __restrict__ bhh,
                            int nsplit) {
    int bid = blockIdx.x;
    int tid = threadIdx.x;
    if (bid < nsplit) {
        size_t i = (size_t)bid * 256 + tid;
        float4 v = x4[i];
        int c = (int)(i % 192) * 4;
        v.x *= g_scale[c + 0]; v.y *= g_scale[c + 1];
        v.z *= g_scale[c + 2]; v.w *= g_scale[c + 3];
        __half2* ph = (__half2*)g_xh;
        ph[i * 2 + 0] = __halves2half2(__float2half(v.x), __float2half(v.y));
        ph[i * 2 + 1] = __halves2half2(__float2half(v.z), __float2half(v.w));
    } else if (bid < nsplit + 4608) {
        int idx = (bid - nsplit) * 256 + tid;      // < 1536*768
        int d = idx % 768;
        int n = idx / 768;
        int g = n % 3, j = n / 3;
        int dir = j >> 8, jj = j & 255;
        int grow = (g == 0) ? jj : (g == 1 ? 512 + jj : 768 + jj);
        float v = w[(size_t)(dir * 1024 + grow) * 768 + d];
        g_W0[idx] = __float2half(v);
    } else {
        int warpId = (bid - nsplit - 4608) * 8 + (tid >> 5);   // < 1536
        int lane = tid & 31;
        int g = warpId % 3, j = warpId / 3;
        int dir = j >> 8, jj = j & 255;
        int grow = (g == 0) ? jj : (g == 1 ? 512 + jj : 768 + jj);
        const float* wr = w + (size_t)(dir * 1024 + grow) * 768;
        float s = 0.f;
        for (int k = lane; k < 768; k += 32) s += g_shift[k] * wr[k];
        #pragma unroll
        for (int o = 16; o; o >>= 1) s += __shfl_down_sync(0xffffffffu, s, o);
        if (!lane) g_gc0[warpId] = s + bih[dir * 1024 + grow] + bhh[dir * 1024 + grow];
    }
}

// ------------- merged L1 prep: repackW1(fp16) + gconst1 + e-bias init --------
__global__ void prep_l1(const float* __restrict__ w,
                        const float* __restrict__ bih,
                        const float* __restrict__ bhh,
                        const float* __restrict__ fcb,
                        float* __restrict__ e, int nrows) {
    int bid = blockIdx.x;
    int tid = threadIdx.x;
    if (bid < 3072) {
        int idx = bid * 256 + tid;                 // < 1536*512
        int d = idx % 512;
        int n = idx / 512;
        int g = n % 3, j = n / 3;
        int dir = j >> 8, jj = j & 255;
        int grow = (g == 0) ? jj : (g == 1 ? 512 + jj : 768 + jj);
        float v = w[(size_t)(dir * 1024 + grow) * 512 + d];
        g_W1[idx] = __float2half(v);
    } else if (bid < 3078) {
        int n = (bid - 3072) * 256 + tid;
        if (n >= 1536) return;
        int g = n % 3, j = n / 3;
        int dir = j >> 8, jj = j & 255;
        int grow = (g == 0) ? jj : (g == 1 ? 512 + jj : 768 + jj);
        g_gc1[n] = bih[dir * 1024 + grow] + bhh[dir * 1024 + grow];
    } else {
        int row = (bid - 3078) * 256 + tid;        // e bias init
        if (row < nrows) {
            e[(size_t)row * 2 + 0] = fcb[0];
            e[(size_t)row * 2 + 1] = fcb[1];
        }
    }
}

// ---------------- HMMA GEMM + fused LSTM (+FC for L1) epilogue --------------
// CTA 128 rows x 192 gate cols, 8 warps (2M x 4N), warp 64x48.
// Single fp16 product: acc += X*W. K-chunk 64, 2-stage pipeline, 2 CTAs/SM.
// Stage (stride 144B): A 128x144=18432 + B 192x144=27648 -> GBUF=46080.
#define GBUF   46080
#define OFF_B  18432
#define SMEM_TC 102400   // epilogue [128][200] floats dominates (2*GBUF=92160)

template <bool L0>
__global__ void __launch_bounds__(256, 2) gemm_lstm_tc(
        const float* __restrict__ fcw, float* __restrict__ e) {
    constexpr int K = L0 ? 768 : 512;
    constexpr int NCH = K / 64;
    const __half* __restrict__ Ah = L0 ? g_xh : g_h1h;
    const __half* __restrict__ Bw = L0 ? g_W0 : g_W1;
    const float* __restrict__ gc = L0 ? g_gc0 : g_gc1;

    extern __shared__ char smem[];
    uint32_t sbase = (uint32_t)__cvta_generic_to_shared(smem);

    const int tid = threadIdx.x;
    const int m0 = blockIdx.y * 128;
    const int n0 = blockIdx.x * 192;

    auto issue = [&](int kt, int b) {
        uint32_t sA = sbase + b * GBUF;
        const int r0 = tid >> 3, q = (tid & 7);
        #pragma unroll
        for (int it = 0; it < 4; ++it) {   // A: 128 rows x 8 x16B = 1024 transfers
            int r = r0 + it * 32;
            uint32_t d = sA + r * 144 + q * 16;
            const size_t go = (size_t)(m0 + r) * K + kt + q * 8;
            cpasync16(d, Ah + go);
        }
        #pragma unroll
        for (int it = 0; it < 6; ++it) {   // B: 192 rows x 8 x16B = 1536 transfers
            int r = r0 + it * 32;
            uint32_t d = sA + OFF_B + r * 144 + q * 16;
            const size_t go = (size_t)(n0 + r) * K + kt + q * 8;
            cpasync16(d, Bw + go);
        }
        CP_COMMIT();
    };

    const int lane = tid & 31, wid = tid >> 5;
    const int wm = (wid & 1) * 64;
    const int wn = (wid >> 1) * 48;

    const int msel   = lane >> 3;
    const int arow_f = (msel & 1) * 8 + (lane & 7);
    const int akoff  = (msel >> 1) * 8;
    const int brow_f = (msel >> 1) * 8 + (lane & 7);
    const int bkoff  = (msel & 1) * 8;

    float acc[4][6][4];
    #pragma unroll
    for (int mt = 0; mt < 4; mt++)
        #pragma unroll
        for (int nb = 0; nb < 6; nb++)
            #pragma unroll
            for (int r = 0; r < 4; r++) acc[mt][nb][r] = 0.f;

    issue(0, 0);
    issue(64, 1);

    #pragma unroll 1
    for (int c = 0; c < NCH; ++c) {
        asm volatile("cp.async.wait_group 1;" ::: "memory");
        __syncthreads();
        uint32_t sA = sbase + (c & 1) * GBUF;

        #pragma unroll
        for (int ks = 0; ks < 64; ks += 16) {
            uint32_t bw[6][2];
            #pragma unroll
            for (int p = 0; p < 3; p++) {
                uint32_t bd = sA + OFF_B + (wn + p * 16 + brow_f) * 144 + (ks + bkoff) * 2;
                ldsm4(bw[2 * p][0], bw[2 * p][1], bw[2 * p + 1][0], bw[2 * p + 1][1], bd);
            }
            #pragma unroll
            for (int mt = 0; mt < 4; mt++) {
                uint32_t ah[4];
                uint32_t ad = sA + (wm + mt * 16 + arow_f) * 144 + (ks + akoff) * 2;
                ldsm4(ah[0], ah[1], ah[2], ah[3], ad);
                #pragma unroll
                for (int nb = 0; nb < 6; nb++)
                    mma16816h(acc[mt][nb], ah, bw[nb]);
            }
        }
        __syncthreads();
        if (c + 2 < NCH) issue((c + 2) * 64, c & 1);
        else             CP_COMMIT();          // keep wait count uniform
    }

    float* sC = (float*)smem;
    #pragma unroll
    for (int mt = 0; mt < 4; mt++)
        #pragma unroll
        for (int nb = 0; nb < 6; nb++) {
            int r = wm + mt * 16 + (lane >> 2);
            int cc = wn + nb * 8 + (lane & 3) * 2;
            sC[r * 200 + cc]           = acc[mt][nb][0];
            sC[r * 200 + cc + 1]       = acc[mt][nb][1];
            sC[(r + 8) * 200 + cc]     = acc[mt][nb][2];
            sC[(r + 8) * 200 + cc + 1] = acc[mt][nb][3];
        }
    __syncthreads();

    const int cb = blockIdx.x * 64;
    const int jj = tid & 63;
    float w0 = 0.f, w1 = 0.f;
    if (!L0) {
        w0 = fcw[cb + jj];
        w1 = fcw[512 + cb + jj];
    }

    #pragma unroll
    for (int t = 0; t < 32; t++) {
        int idx = t * 256 + tid;
        int r = idx >> 6, j = idx & 63;
        float iv = sC[r * 200 + 3 * j + 0] + gc[n0 + 3 * j + 0];
        float gv = sC[r * 200 + 3 * j + 1] + gc[n0 + 3 * j + 1];
        float ov = sC[r * 200 + 3 * j + 2] + gc[n0 + 3 * j + 2];
        float cv = fsigmoid(iv) * ftanh(gv);
        float hv = fsigmoid(ov) * ftanh(cv);
        if (L0) {
            g_h1h[(size_t)(m0 + r) * 512 + cb + j] = __float2half(hv);
        } else {
            float p0 = hv * w0, p1 = hv * w1;
            #pragma unroll
            for (int o = 16; o; o >>= 1) {
                p0 += __shfl_down_sync(0xffffffffu, p0, o);
                p1 += __shfl_down_sync(0xffffffffu, p1, o);
            }
            if (lane == 0) {
                atomicAdd(&e[(size_t)(m0 + r) * 2 + 0], p0);
                atomicAdd(&e[(size_t)(m0 + r) * 2 + 1], p1);
            }
        }
    }
}

// ---------------- CRF NLL: parallel log-semiring reduce ----------------------
__device__ __forceinline__ double lse2(double a, double b) {
    double m = fmax(a, b), n = fmin(a, b);
    return m + log1p(exp(n - m));
}

__global__ __launch_bounds__(256)
void crf_part(const float* __restrict__ e, const int* __restrict__ tags,
              const float* __restrict__ trans, int N) {
    __shared__ double sP[256][4];
    __shared__ double sN[256];
    const int t = threadIdx.x;
    const long n = (long)blockIdx.x * 256 + t;
    const double T00 = trans[0], T01 = trans[1], T10 = trans[2], T11 = trans[3];
    const double NEG = -1e30;

    double m00 = 0.0, m01 = NEG, m10 = NEG, m11 = 0.0;
    double np = 0.0;
    if (n < N) {
        int tg = tags[n];
        np = (double)e[n * 2 + tg];
        if (n >= 1) {
            int tp = tags[n - 1];
            np += (tp == 0) ? (tg == 0 ? T00 : T01) : (tg == 0 ? T10 : T11);
            double e0 = (double)e[n * 2 + 0];
            double e1 = (double)e[n * 2 + 1];
            m00 = T00 + e0; m01 = T01 + e1;
            m10 = T10 + e0; m11 = T11 + e1;
        }
    }
    sP[t][0] = m00; sP[t][1] = m01; sP[t][2] = m10; sP[t][3] = m11;
    sN[t] = np;
    __syncthreads();

    for (int half = 128; half >= 1; half >>= 1) {
        double a0, a1, a2, a3, b0, b1, b2, b3, nn;
        bool act = t < half;
        if (act) {
            a0 = sP[2 * t][0];     a1 = sP[2 * t][1];
            a2 = sP[2 * t][2];     a3 = sP[2 * t][3];
            b0 = sP[2 * t + 1][0]; b1 = sP[2 * t + 1][1];
            b2 = sP[2 * t + 1][2]; b3 = sP[2 * t + 1][3];
            nn = sN[2 * t] + sN[2 * t + 1];
        }
        __syncthreads();
        if (act) {
            sP[t][0] = lse2(a0 + b0, a1 + b2);
            sP[t][1] = lse2(a0 + b1, a1 + b3);
            sP[t][2] = lse2(a2 + b0, a3 + b2);
            sP[t][3] = lse2(a2 + b1, a3 + b3);
            sN[t] = nn;
        }
        __syncthreads();
    }
    if (t == 0) {
        g_crfP[blockIdx.x][0] = sP[0][0];
        g_crfP[blockIdx.x][1] = sP[0][1];
        g_crfP[blockIdx.x][2] = sP[0][2];
        g_crfP[blockIdx.x][3] = sP[0][3];
        g_crfN[blockIdx.x] = sN[0];
    }
}

__global__ __launch_bounds__(256)
void crf_comb(const float* __restrict__ e, const int* __restrict__ tags,
              const float* __restrict__ startv, const float* __restrict__ endv,
              float* __restrict__ loss_out, int N, int nb) {
    __shared__ double sP[256][4];
    __shared__ double sN[256];
    const int t = threadIdx.x;
    const double NEG = -1e30;
    if (t < nb) {
        sP[t][0] = g_crfP[t][0]; sP[t][1] = g_crfP[t][1];
        sP[t][2] = g_crfP[t][2]; sP[t][3] = g_crfP[t][3];
        sN[t] = g_crfN[t];
    } else {
        sP[t][0] = 0.0; sP[t][1] = NEG; sP[t][2] = NEG; sP[t][3] = 0.0;
        sN[t] = 0.0;
    }
    __syncthreads();

    for (int half = 128; half >= 1; half >>= 1) {
        double a0, a1, a2, a3, b0, b1, b2, b3, nn;
        bool act = t < half;
        if (act) {
            a0 = sP[2 * t][0];     a1 = sP[2 * t][1];
            a2 = sP[2 * t][2];     a3 = sP[2 * t][3];
            b0 = sP[2 * t + 1][0]; b1 = sP[2 * t + 1][1];
            b2 = sP[2 * t + 1][2]; b3 = sP[2 * t + 1][3];
            nn = sN[2 * t] + sN[2 * t + 1];
        }
        __syncthreads();
        if (act) {
            sP[t][0] = lse2(a0 + b0, a1 + b2);
            sP[t][1] = lse2(a0 + b1, a1 + b3);
            sP[t][2] = lse2(a2 + b0, a3 + b2);
            sP[t][3] = lse2(a2 + b1, a3 + b3);
            sN[t] = nn;
        }
        __syncthreads();
    }

    if (t == 0) {
        double num = sN[0] + (double)startv[tags[0]] + (double)endv[tags[N - 1]];
        double a0 = (double)startv[0] + (double)e[0];
        double a1 = (double)startv[1] + (double)e[1];
        double f0 = lse2(a0 + sP[0][0], a1 + sP[0][2]);
        double f1 = lse2(a0 + sP[0][1], a1 + sP[0][3]);
        double den = lse2(f0 + (double)endv[0], f1 + (double)endv[1]);
        loss_out[0] = (float)(den - num);
    }
}

// ---------------- launch ----------------
extern "C" void kernel_launch(void* const* d_in, const int* in_sizes, int n_in,
                              void* d_out, int out_size) {
    const float* x        = (const float*)d_in[0];
    const float* gamma    = (const float*)d_in[1];
    const float* beta     = (const float*)d_in[2];
    const float* w_ih_l0  = (const float*)d_in[3];
    const float* b_ih_l0  = (const float*)d_in[5];
    const float* b_hh_l0  = (const float*)d_in[6];
    const float* w_ih_l1  = (const float*)d_in[7];
    const float* b_ih_l1  = (const float*)d_in[9];
    const float* b_hh_l1  = (const float*)d_in[10];
    const float* fc_w     = (const float*)d_in[11];
    const float* fc_b     = (const float*)d_in[12];
    const float* crf_start= (const float*)d_in[13];
    const float* crf_end  = (const float*)d_in[14];
    const float* crf_trans= (const float*)d_in[15];
    const int*   labels   = (const int*)d_in[16];

    int N = in_sizes[0] / 768;      // 65536
    float* out = (float*)d_out;
    float* e = out + 1;

    cudaFuncSetAttribute((const void*)gemm_lstm_tc<true>,
                         cudaFuncAttributeMaxDynamicSharedMemorySize, SMEM_TC);
    cudaFuncSetAttribute((const void*)gemm_lstm_tc<false>,
                         cudaFuncAttributeMaxDynamicSharedMemorySize, SMEM_TC);

    int rpb = (N + 127) / 128;
    int nblk = (N + rpb - 1) / rpb;
    int nsplit = N * 768 / 4 / 256;                        // 49152

    stats_kernel<<<nblk, 768>>>(x, rpb, N);                                    // 0
    prep_kernel<<<1, 768>>>(gamma, beta, N, nblk);                             // 1
    prep_all_l0<<<nsplit + 4608 + 192, 256>>>((const float4*)x, w_ih_l0,
                                              b_ih_l0, b_hh_l0, nsplit);       // 2
    dim3 gg(8, N / 128);
    gemm_lstm_tc<true ><<<gg, 256, SMEM_TC>>>(fc_w, e);                        // 3  <- ncu
    prep_l1<<<3078 + (N + 255) / 256, 256>>>(w_ih_l1, b_ih_l1, b_hh_l1,
                                             fc_b, e, N);                      // 4
    gemm_lstm_tc<false><<<gg, 256, SMEM_TC>>>(fc_w, e);                        // 5
    crf_part<<<(N + 255) / 256, 256>>>(e, labels, crf_trans, N);               // 6
    crf_comb<<<1, 256>>>(e, labels, crf_start, crf_end, out, N, (N + 255) / 256); // 7
}

// round 17
// speedup vs baseline: 1.0301x; 1.0301x over previous
#include <cuda_runtime.h>
#include <cuda_fp16.h>
#include <math.h>
#include <stdint.h>

#define NROWS 65536

// ---------------- scratch (device globals; no allocation allowed) ----------
__device__ float  g_psum[128 * 768];
__device__ float  g_psumsq[128 * 768];
__device__ float  g_scale[768];
__device__ float  g_shift[768];
__device__ __half g_xh[(size_t)NROWS * 768];
__device__ __half g_W0[1536 * 768];
__device__ __half g_W1[1536 * 512];
__device__ __half g_h1h[(size_t)NROWS * 512];
__device__ float g_gc0[1536];
__device__ float g_gc1[1536];
__device__ double g_crfP[256][4];
__device__ double g_crfN[256];

// ---------------- helpers ----------------
__device__ __forceinline__ void cpasync16(uint32_t dst, const void* src) {
    asm volatile("cp.async.cg.shared.global [%0], [%1], 16;" :: "r"(dst), "l"(src));
}
#define CP_COMMIT() asm volatile("cp.async.commit_group;")

__device__ __forceinline__ void ldsm4(uint32_t& r0, uint32_t& r1, uint32_t& r2,
                                      uint32_t& r3, uint32_t addr) {
    asm volatile("ldmatrix.sync.aligned.m8n8.x4.shared.b16 {%0,%1,%2,%3}, [%4];"
                 : "=r"(r0), "=r"(r1), "=r"(r2), "=r"(r3) : "r"(addr));
}
__device__ __forceinline__ void mma16816h(float* c, const uint32_t* a, const uint32_t* b) {
    asm volatile("mma.sync.aligned.m16n8k16.row.col.f32.f16.f16.f32 "
                 "{%0,%1,%2,%3}, {%4,%5,%6,%7}, {%8,%9}, {%0,%1,%2,%3};"
                 : "+f"(c[0]), "+f"(c[1]), "+f"(c[2]), "+f"(c[3])
                 : "r"(a[0]), "r"(a[1]), "r"(a[2]), "r"(a[3]), "r"(b[0]), "r"(b[1]));
}

// ---------------- BN stats (per-block partials) -----------------------------
__global__ void stats_kernel(const float* __restrict__ x, int rowsPerBlock, int nrows) {
    int c = threadIdx.x;
    int b = blockIdx.x;
    long r0 = (long)b * rowsPerBlock;
    float s = 0.f, s2 = 0.f;
    for (int r = 0; r < rowsPerBlock; ++r) {
        long row = r0 + r;
        if (row < nrows) {
            float v = x[row * 768 + c];
            s += v; s2 += v * v;
        }
    }
    g_psum[b * 768 + c] = s;
    g_psumsq[b * 768 + c] = s2;
}

__global__ void prep_kernel(const float* __restrict__ gamma,
                            const float* __restrict__ beta, int nrows, int nblk) {
    int c = threadIdx.x;
    double s = 0.0, s2 = 0.0;
    for (int b = 0; b < nblk; ++b) {
        s  += (double)g_psum[b * 768 + c];
        s2 += (double)g_psumsq[b * 768 + c];
    }
    double mean = s / (double)nrows;
    double var  = s2 / (double)nrows - mean * mean;
    float sc = gamma[c] * (float)(1.0 / sqrt(var + 1e-5));
    g_scale[c] = sc;
    g_shift[c] = beta[c] - (float)mean * sc;
}

// ------------- merged L0 prep: split_x(fp16) + repackW0(fp16) + gconst0 ------
__global__ void prep_all_l0(const float4* __restrict__ x4,
                            const float* __restrict__ w,
                            const float* __restrict__ bih,
                            const float* __restrict__ bhh,
                            int nsplit) {
    int bid = blockIdx.x;
    int tid = threadIdx.x;
    if (bid < nsplit) {
        size_t i = (size_t)bid * 256 + tid;
        float4 v = x4[i];
        int c = (int)(i % 192) * 4;
        v.x *= g_scale[c + 0]; v.y *= g_scale[c + 1];
        v.z *= g_scale[c + 2]; v.w *= g_scale[c + 3];
        __half2* ph = (__half2*)g_xh;
        ph[i * 2 + 0] = __halves2half2(__float2half(v.x), __float2half(v.y));
        ph[i * 2 + 1] = __halves2half2(__float2half(v.z), __float2half(v.w));
    } else if (bid < nsplit + 4608) {
        int idx = (bid - nsplit) * 256 + tid;      // < 1536*768
        int d = idx % 768;
        int n = idx / 768;
        int g = n % 3, j = n / 3;
        int dir = j >> 8, jj = j & 255;
        int grow = (g == 0) ? jj : (g == 1 ? 512 + jj : 768 + jj);
        float v = w[(size_t)(dir * 1024 + grow) * 768 + d];
        g_W0[idx] = __float2half(v);
    } else {
        int warpId = (bid - nsplit - 4608) * 8 + (tid >> 5);   // < 1536
        int lane = tid & 31;
        int g = warpId % 3, j = warpId / 3;
        int dir = j >> 8, jj = j & 255;
        int grow = (g == 0) ? jj : (g == 1 ? 512 + jj : 768 + jj);
        const float* wr = w + (size_t)(dir * 1024 + grow) * 768;
        float s = 0.f;
        for (int k = lane; k < 768; k += 32) s += g_shift[k] * wr[k];
        #pragma unroll
        for (int o = 16; o; o >>= 1) s += __shfl_down_sync(0xffffffffu, s, o);
        if (!lane) g_gc0[warpId] = s + bih[dir * 1024 + grow] + bhh[dir * 1024 + grow];
    }
}

// ------------- merged L1 prep: repackW1(fp16) + gconst1 + e-bias init --------
__global__ void prep_l1(const float* __restrict__ w,
                        const float* __restrict__ bih,
                        const float* __restrict__ bhh,
                        const float* __restrict__ fcb,
                        float* __restrict__ e, int nrows) {
    int bid = blockIdx.x;
    int tid = threadIdx.x;
    if (bid < 3072) {
        int idx = bid * 256 + tid;                 // < 1536*512
        int d = idx % 512;
        int n = idx / 512;
        int g = n % 3, j = n / 3;
        int dir = j >> 8, jj = j & 255;
        int grow = (g == 0) ? jj : (g == 1 ? 512 + jj : 768 + jj);
        float v = w[(size_t)(dir * 1024 + grow) * 512 + d];
        g_W1[idx] = __float2half(v);
    } else if (bid < 3078) {
        int n = (bid - 3072) * 256 + tid;
        if (n >= 1536) return;
        int g = n % 3, j = n / 3;
        int dir = j >> 8, jj = j & 255;
        int grow = (g == 0) ? jj : (g == 1 ? 512 + jj : 768 + jj);
        g_gc1[n] = bih[dir * 1024 + grow] + bhh[dir * 1024 + grow];
    } else {
        int row = (bid - 3078) * 256 + tid;        // e bias init
        if (row < nrows) {
            e[(size_t)row * 2 + 0] = fcb[0];
            e[(size_t)row * 2 + 1] = fcb[1];
        }
    }
}

// ---------------- HMMA GEMM + fused LSTM (+FC for L1) epilogue --------------
// CTA 128 rows x 192 gate cols, 8 warps (2M x 4N), warp 64x48.
// Single fp16 product: acc += X*W. K-chunk 64, 2-stage pipeline, 2 CTAs/SM.
// Stage (stride 144B): A 128x144=18432 + B 192x144=27648 -> GBUF=46080.
// Global src offsets + smem dsts precomputed once; issue() is add-only.
#define GBUF   46080
#define OFF_B  18432
#define SMEM_TC 102400   // epilogue [128][200] floats dominates (2*GBUF=92160)

template <bool L0>
__global__ void __launch_bounds__(256, 2) gemm_lstm_tc(
        const float* __restrict__ fcw, float* __restrict__ e) {
    constexpr int K = L0 ? 768 : 512;
    constexpr int NCH = K / 64;
    const __half* __restrict__ Ah = L0 ? g_xh : g_h1h;
    const __half* __restrict__ Bw = L0 ? g_W0 : g_W1;
    const float* __restrict__ gc = L0 ? g_gc0 : g_gc1;

    extern __shared__ char smem[];
    uint32_t sbase = (uint32_t)__cvta_generic_to_shared(smem);

    const int tid = threadIdx.x;
    const int m0 = blockIdx.y * 128;
    const int n0 = blockIdx.x * 192;

    // -------- precomputed transfer descriptors (loop-invariant) ------------
    const int r0 = tid >> 3, q = tid & 7;
    uint32_t aoff[4], boff[6];          // global element offsets (32-bit)
    uint32_t adst[4], bdst[6];          // smem dsts for buffer 0
    #pragma unroll
    for (int it = 0; it < 4; ++it) {
        int r = r0 + it * 32;
        aoff[it] = (uint32_t)((m0 + r) * K + q * 8);
        adst[it] = sbase + r * 144 + q * 16;
    }
    #pragma unroll
    for (int it = 0; it < 6; ++it) {
        int r = r0 + it * 32;
        boff[it] = (uint32_t)((n0 + r) * K + q * 8);
        bdst[it] = sbase + OFF_B + r * 144 + q * 16;
    }

    auto issue = [&](int kt, int b) {
        uint32_t bo = b * GBUF;
        #pragma unroll
        for (int it = 0; it < 4; ++it)
            cpasync16(adst[it] + bo, Ah + aoff[it] + kt);
        #pragma unroll
        for (int it = 0; it < 6; ++it)
            cpasync16(bdst[it] + bo, Bw + boff[it] + kt);
        CP_COMMIT();
    };

    const int lane = tid & 31, wid = tid >> 5;
    const int wm = (wid & 1) * 64;
    const int wn = (wid >> 1) * 48;

    const int msel   = lane >> 3;
    const int arow_f = (msel & 1) * 8 + (lane & 7);
    const int akoff  = (msel >> 1) * 8;
    const int brow_f = (msel >> 1) * 8 + (lane & 7);
    const int bkoff  = (msel & 1) * 8;

    float acc[4][6][4];
    #pragma unroll
    for (int mt = 0; mt < 4; mt++)
        #pragma unroll
        for (int nb = 0; nb < 6; nb++)
            #pragma unroll
            for (int r = 0; r < 4; r++) acc[mt][nb][r] = 0.f;

    issue(0, 0);
    issue(64, 1);

    #pragma unroll 1
    for (int c = 0; c < NCH; ++c) {
        asm volatile("cp.async.wait_group 1;" ::: "memory");
        __syncthreads();
        uint32_t sA = sbase + (c & 1) * GBUF;

        #pragma unroll
        for (int ks = 0; ks < 64; ks += 16) {
            uint32_t bw[6][2];
            #pragma unroll
            for (int p = 0; p < 3; p++) {
                uint32_t bd = sA + OFF_B + (wn + p * 16 + brow_f) * 144 + (ks + bkoff) * 2;
                ldsm4(bw[2 * p][0], bw[2 * p][1], bw[2 * p + 1][0], bw[2 * p + 1][1], bd);
            }
            #pragma unroll
            for (int mt = 0; mt < 4; mt++) {
                uint32_t ah[4];
                uint32_t ad = sA + (wm + mt * 16 + arow_f) * 144 + (ks + akoff) * 2;
                ldsm4(ah[0], ah[1], ah[2], ah[3], ad);
                #pragma unroll
                for (int nb = 0; nb < 6; nb++)
                    mma16816h(acc[mt][nb], ah, bw[nb]);
            }
        }
        __syncthreads();
        if (c + 2 < NCH) issue((c + 2) * 64, c & 1);
        else             CP_COMMIT();          // keep wait count uniform
    }

    float* sC = (float*)smem;
    #pragma unroll
    for (int mt = 0; mt < 4; mt++)
        #pragma unroll
        for (int nb = 0; nb < 6; nb++) {
            int r = wm + mt * 16 + (lane >> 2);
            int cc = wn + nb * 8 + (lane & 3) * 2;
            sC[r * 200 + cc]           = acc[mt][nb][0];
            sC[r * 200 + cc + 1]       = acc[mt][nb][1];
            sC[(r + 8) * 200 + cc]     = acc[mt][nb][2];
            sC[(r + 8) * 200 + cc + 1] = acc[mt][nb][3];
        }
    __syncthreads();

    const int cb = blockIdx.x * 64;
    const int jj = tid & 63;
    float w0 = 0.f, w1 = 0.f;
    if (!L0) {
        w0 = fcw[cb + jj];
        w1 = fcw[512 + cb + jj];
    }

    #pragma unroll
    for (int t = 0; t < 32; t++) {
        int idx = t * 256 + tid;
        int r = idx >> 6, j = idx & 63;
        float iv = sC[r * 200 + 3 * j + 0] + gc[n0 + 3 * j + 0];
        float gv = sC[r * 200 + 3 * j + 1] + gc[n0 + 3 * j + 1];
        float ov = sC[r * 200 + 3 * j + 2] + gc[n0 + 3 * j + 2];
        float cv = (1.f / (1.f + expf(-iv))) * tanhf(gv);
        float hv = (1.f / (1.f + expf(-ov))) * tanhf(cv);
        if (L0) {
            g_h1h[(size_t)(m0 + r) * 512 + cb + j] = __float2half(hv);
        } else {
            float p0 = hv * w0, p1 = hv * w1;
            #pragma unroll
            for (int o = 16; o; o >>= 1) {
                p0 += __shfl_down_sync(0xffffffffu, p0, o);
                p1 += __shfl_down_sync(0xffffffffu, p1, o);
            }
            if (lane == 0) {
                atomicAdd(&e[(size_t)(m0 + r) * 2 + 0], p0);
                atomicAdd(&e[(size_t)(m0 + r) * 2 + 1], p1);
            }
        }
    }
}

// ---------------- CRF NLL: parallel log-semiring reduce ----------------------
__device__ __forceinline__ double lse2(double a, double b) {
    double m = fmax(a, b), n = fmin(a, b);
    return m + log1p(exp(n - m));
}

__global__ __launch_bounds__(256)
void crf_part(const float* __restrict__ e, const int* __restrict__ tags,
              const float* __restrict__ trans, int N) {
    __shared__ double sP[256][4];
    __shared__ double sN[256];
    const int t = threadIdx.x;
    const long n = (long)blockIdx.x * 256 + t;
    const double T00 = trans[0], T01 = trans[1], T10 = trans[2], T11 = trans[3];
    const double NEG = -1e30;

    double m00 = 0.0, m01 = NEG, m10 = NEG, m11 = 0.0;
    double np = 0.0;
    if (n < N) {
        int tg = tags[n];
        np = (double)e[n * 2 + tg];
        if (n >= 1) {
            int tp = tags[n - 1];
            np += (tp == 0) ? (tg == 0 ? T00 : T01) : (tg == 0 ? T10 : T11);
            double e0 = (double)e[n * 2 + 0];
            double e1 = (double)e[n * 2 + 1];
            m00 = T00 + e0; m01 = T01 + e1;
            m10 = T10 + e0; m11 = T11 + e1;
        }
    }
    sP[t][0] = m00; sP[t][1] = m01; sP[t][2] = m10; sP[t][3] = m11;
    sN[t] = np;
    __syncthreads();

    for (int half = 128; half >= 1; half >>= 1) {
        double a0, a1, a2, a3, b0, b1, b2, b3, nn;
        bool act = t < half;
        if (act) {
            a0 = sP[2 * t][0];     a1 = sP[2 * t][1];
            a2 = sP[2 * t][2];     a3 = sP[2 * t][3];
            b0 = sP[2 * t + 1][0]; b1 = sP[2 * t + 1][1];
            b2 = sP[2 * t + 1][2]; b3 = sP[2 * t + 1][3];
            nn = sN[2 * t] + sN[2 * t + 1];
        }
        __syncthreads();
        if (act) {
            sP[t][0] = lse2(a0 + b0, a1 + b2);
            sP[t][1] = lse2(a0 + b1, a1 + b3);
            sP[t][2] = lse2(a2 + b0, a3 + b2);
            sP[t][3] = lse2(a2 + b1, a3 + b3);
            sN[t] = nn;
        }
        __syncthreads();
    }
    if (t == 0) {
        g_crfP[blockIdx.x][0] = sP[0][0];
        g_crfP[blockIdx.x][1] = sP[0][1];
        g_crfP[blockIdx.x][2] = sP[0][2];
        g_crfP[blockIdx.x][3] = sP[0][3];
        g_crfN[blockIdx.x] = sN[0];
    }
}

__global__ __launch_bounds__(256)
void crf_comb(const float* __restrict__ e, const int* __restrict__ tags,
              const float* __restrict__ startv, const float* __restrict__ endv,
              float* __restrict__ loss_out, int N, int nb) {
    __shared__ double sP[256][4];
    __shared__ double sN[256];
    const int t = threadIdx.x;
    const double NEG = -1e30;
    if (t < nb) {
        sP[t][0] = g_crfP[t][0]; sP[t][1] = g_crfP[t][1];
        sP[t][2] = g_crfP[t][2]; sP[t][3] = g_crfP[t][3];
        sN[t] = g_crfN[t];
    } else {
        sP[t][0] = 0.0; sP[t][1] = NEG; sP[t][2] = NEG; sP[t][3] = 0.0;
        sN[t] = 0.0;
    }
    __syncthreads();

    for (int half = 128; half >= 1; half >>= 1) {
        double a0, a1, a2, a3, b0, b1, b2, b3, nn;
        bool act = t < half;
        if (act) {
            a0 = sP[2 * t][0];     a1 = sP[2 * t][1];
            a2 = sP[2 * t][2];     a3 = sP[2 * t][3];
            b0 = sP[2 * t + 1][0]; b1 = sP[2 * t + 1][1];
            b2 = sP[2 * t + 1][2]; b3 = sP[2 * t + 1][3];
            nn = sN[2 * t] + sN[2 * t + 1];
        }
        __syncthreads();
        if (act) {
            sP[t][0] = lse2(a0 + b0, a1 + b2);
            sP[t][1] = lse2(a0 + b1, a1 + b3);
            sP[t][2] = lse2(a2 + b0, a3 + b2);
            sP[t][3] = lse2(a2 + b1, a3 + b3);
            sN[t] = nn;
        }
        __syncthreads();
    }

    if (t == 0) {
        double num = sN[0] + (double)startv[tags[0]] + (double)endv[tags[N - 1]];
        double a0 = (double)startv[0] + (double)e[0];
        double a1 = (double)startv[1] + (double)e[1];
        double f0 = lse2(a0 + sP[0][0], a1 + sP[0][2]);
        double f1 = lse2(a0 + sP[0][1], a1 + sP[0][3]);
        double den = lse2(f0 + (double)endv[0], f1 + (double)endv[1]);
        loss_out[0] = (float)(den - num);
    }
}

// ---------------- launch ----------------
extern "C" void kernel_launch(void* const* d_in, const int* in_sizes, int n_in,
                              void* d_out, int out_size) {
    const float* x        = (const float*)d_in[0];
    const float* gamma    = (const float*)d_in[1];
    const float* beta     = (const float*)d_in[2];
    const float* w_ih_l0  = (const float*)d_in[3];
    const float* b_ih_l0  = (const float*)d_in[5];
    const float* b_hh_l0  = (const float*)d_in[6];
    const float* w_ih_l1  = (const float*)d_in[7];
    const float* b_ih_l1  = (const float*)d_in[9];
    const float* b_hh_l1  = (const float*)d_in[10];
    const float* fc_w     = (const float*)d_in[11];
    const float* fc_b     = (const float*)d_in[12];
    const float* crf_start= (const float*)d_in[13];
    const float* crf_end  = (const float*)d_in[14];
    const float* crf_trans= (const float*)d_in[15];
    const int*   labels   = (const int*)d_in[16];

    int N = in_sizes[0] / 768;      // 65536
    float* out = (float*)d_out;
    float* e = out + 1;

    cudaFuncSetAttribute((const void*)gemm_lstm_tc<true>,
                         cudaFuncAttributeMaxDynamicSharedMemorySize, SMEM_TC);
    cudaFuncSetAttribute((const void*)gemm_lstm_tc<false>,
                         cudaFuncAttributeMaxDynamicSharedMemorySize, SMEM_TC);

    int rpb = (N + 127) / 128;
    int nblk = (N + rpb - 1) / rpb;
    int nsplit = N * 768 / 4 / 256;                        // 49152

    stats_kernel<<<nblk, 768>>>(x, rpb, N);                                    // 0
    prep_kernel<<<1, 768>>>(gamma, beta, N, nblk);                             // 1
    prep_all_l0<<<nsplit + 4608 + 192, 256>>>((const float4*)x, w_ih_l0,
                                              b_ih_l0, b_hh_l0, nsplit);       // 2
    dim3 gg(8, N / 128);
    gemm_lstm_tc<true ><<<gg, 256, SMEM_TC>>>(fc_w, e);                        // 3  <- ncu
    prep_l1<<<3078 + (N + 255) / 256, 256>>>(w_ih_l1, b_ih_l1, b_hh_l1,
                                             fc_b, e, N);                      // 4
    gemm_lstm_tc<false><<<gg, 256, SMEM_TC>>>(fc_w, e);                        // 5
    crf_part<<<(N + 255) / 256, 256>>>(e, labels, crf_trans, N);               // 6
    crf_comb<<<1, 256>>>(e, labels, crf_start, crf_end, out, N, (N + 255) / 256); // 7
}